// round 1
// baseline (speedup 1.0000x reference)
#include <cuda_runtime.h>
#include <cuda_bf16.h>
#include <cstdint>

// Merged coefficients: [G=8][10] = 6 numerator + 4 denominator (EPS folded in).
__device__ float g_coef[80];

#define G 8
#define R 3
#define SCALING 2.0f
#define EPS 1e-6f

__global__ void merge_coeffs_kernel(const float* __restrict__ base_num,
                                    const float* __restrict__ base_den,
                                    const float* __restrict__ lA_num,
                                    const float* __restrict__ lB_num,
                                    const float* __restrict__ lA_den,
                                    const float* __restrict__ lB_den) {
    int t = threadIdx.x;
    if (t >= G * 10) return;
    int g = t / 10;
    int k = t % 10;
    float s;
    if (k < 6) {
        s = base_num[g * 6 + k];
        #pragma unroll
        for (int r = 0; r < R; r++)
            s += SCALING * lB_num[g * R + r] * lA_num[r * 6 + k];
    } else {
        int kk = k - 6;
        s = base_den[g * 4 + kk];
        #pragma unroll
        for (int r = 0; r < R; r++)
            s += SCALING * lB_den[g * R + r] * lA_den[r * 4 + kk];
        s += EPS;
    }
    g_coef[t] = s;
}

__device__ __forceinline__ float rational_one(float x, const float* __restrict__ c) {
    // P(x) = a0 + a1 x + ... + a5 x^5 (Horner)
    float p = c[5];
    p = fmaf(p, x, c[4]);
    p = fmaf(p, x, c[3]);
    p = fmaf(p, x, c[2]);
    p = fmaf(p, x, c[1]);
    p = fmaf(p, x, c[0]);
    // Z(x) = b0 + b1 x + b2 x^2 + b3 x^3 (Horner), Q = 1 + |Z*x|
    float z = c[9];
    z = fmaf(z, x, c[8]);
    z = fmaf(z, x, c[7]);
    z = fmaf(z, x, c[6]);
    float q = 1.0f + fabsf(z * x);
    return __fdividef(p, q);
}

// x is [B, L, D] with D = 4096, G = 8 -> Dg = 512 channels/group = 128 float4s.
// For vector index v: group = (v >> 7) & 7.
__global__ void __launch_bounds__(256) nora_kernel(const float4* __restrict__ x,
                                                   float4* __restrict__ out,
                                                   int nvec) {
    __shared__ float sc[80];
    if (threadIdx.x < 80) sc[threadIdx.x] = g_coef[threadIdx.x];
    __syncthreads();

    int v = blockIdx.x * blockDim.x + threadIdx.x;
    if (v >= nvec) return;

    int g = (v >> 7) & 7;
    const float* c = sc + g * 10;

    float4 xi = x[v];
    float4 r;
    r.x = rational_one(xi.x, c);
    r.y = rational_one(xi.y, c);
    r.z = rational_one(xi.z, c);
    r.w = rational_one(xi.w, c);
    out[v] = r;
}

extern "C" void kernel_launch(void* const* d_in, const int* in_sizes, int n_in,
                              void* d_out, int out_size) {
    const float* x        = (const float*)d_in[0];
    const float* base_num = (const float*)d_in[1];
    const float* base_den = (const float*)d_in[2];
    const float* lA_num   = (const float*)d_in[3];
    const float* lB_num   = (const float*)d_in[4];
    const float* lA_den   = (const float*)d_in[5];
    const float* lB_den   = (const float*)d_in[6];
    // d_in[7] = num_groups (known = 8, hardcoded)

    merge_coeffs_kernel<<<1, 96>>>(base_num, base_den, lA_num, lB_num, lA_den, lB_den);

    int n = in_sizes[0];          // 4*4096*4096 = 67108864
    int nvec = n >> 2;            // float4 count, 16777216
    int threads = 256;
    int blocks = (nvec + threads - 1) / threads;
    nora_kernel<<<blocks, threads>>>((const float4*)x, (float4*)d_out, nvec);
}

// round 2
// speedup vs baseline: 1.0514x; 1.0514x over previous
#include <cuda_runtime.h>
#include <cuda_bf16.h>
#include <cstdint>

// Merged coefficients: [G=8][10] = 6 numerator + 4 denominator (EPS folded in).
__device__ float g_coef[80];

#define G 8
#define R 3
#define SCALING 2.0f
#define EPS 1e-6f
#define ILP 4

__global__ void merge_coeffs_kernel(const float* __restrict__ base_num,
                                    const float* __restrict__ base_den,
                                    const float* __restrict__ lA_num,
                                    const float* __restrict__ lB_num,
                                    const float* __restrict__ lA_den,
                                    const float* __restrict__ lB_den) {
    int t = threadIdx.x;
    if (t >= G * 10) return;
    int g = t / 10;
    int k = t % 10;
    float s;
    if (k < 6) {
        s = base_num[g * 6 + k];
        #pragma unroll
        for (int r = 0; r < R; r++)
            s += SCALING * lB_num[g * R + r] * lA_num[r * 6 + k];
    } else {
        int kk = k - 6;
        s = base_den[g * 4 + kk];
        #pragma unroll
        for (int r = 0; r < R; r++)
            s += SCALING * lB_den[g * R + r] * lA_den[r * 4 + kk];
        s += EPS;
    }
    g_coef[t] = s;
}

__device__ __forceinline__ float rational_one(float x, const float* __restrict__ c) {
    // P(x) = a0 + a1 x + ... + a5 x^5 (Horner)
    float p = c[5];
    p = fmaf(p, x, c[4]);
    p = fmaf(p, x, c[3]);
    p = fmaf(p, x, c[2]);
    p = fmaf(p, x, c[1]);
    p = fmaf(p, x, c[0]);
    // Z(x) = b0 + b1 x + b2 x^2 + b3 x^3 (Horner), Q = 1 + |Z*x|
    float z = c[9];
    z = fmaf(z, x, c[8]);
    z = fmaf(z, x, c[7]);
    z = fmaf(z, x, c[6]);
    float q = 1.0f + fabsf(z * x);
    return __fdividef(p, q);
}

// x is [B, L, D], D = 4096, G = 8 -> Dg = 512 channels/group = 128 float4s.
// Group of float4 index v: (v >> 7) & 7.
// Each thread handles ILP=4 block-strided float4s, loads issued back-to-back
// (MLP=4) before any compute to deepen the memory pipeline.
__global__ void __launch_bounds__(256) nora_kernel(const float4* __restrict__ x,
                                                   float4* __restrict__ out,
                                                   int nvec) {
    __shared__ float sc[80];
    if (threadIdx.x < 80) sc[threadIdx.x] = g_coef[threadIdx.x];
    __syncthreads();

    int base = blockIdx.x * (blockDim.x * ILP) + threadIdx.x;

    float4 xi[ILP];
    int    v[ILP];
    #pragma unroll
    for (int k = 0; k < ILP; k++) {
        v[k] = base + k * 256;
        // grid exactly covers nvec (nvec = 16M, divisible); guard for safety
        if (v[k] < nvec) xi[k] = __ldcs(&x[v[k]]);
    }

    #pragma unroll
    for (int k = 0; k < ILP; k++) {
        if (v[k] >= nvec) break;
        const float* c = sc + ((v[k] >> 7) & 7) * 10;
        float4 r;
        r.x = rational_one(xi[k].x, c);
        r.y = rational_one(xi[k].y, c);
        r.z = rational_one(xi[k].z, c);
        r.w = rational_one(xi[k].w, c);
        __stcs(&out[v[k]], r);
    }
}

extern "C" void kernel_launch(void* const* d_in, const int* in_sizes, int n_in,
                              void* d_out, int out_size) {
    const float* x        = (const float*)d_in[0];
    const float* base_num = (const float*)d_in[1];
    const float* base_den = (const float*)d_in[2];
    const float* lA_num   = (const float*)d_in[3];
    const float* lB_num   = (const float*)d_in[4];
    const float* lA_den   = (const float*)d_in[5];
    const float* lB_den   = (const float*)d_in[6];

    merge_coeffs_kernel<<<1, 96>>>(base_num, base_den, lA_num, lB_num, lA_den, lB_den);

    int n = in_sizes[0];          // 67108864
    int nvec = n >> 2;            // 16777216 float4s
    int threads = 256;
    int vecs_per_block = threads * ILP;
    int blocks = (nvec + vecs_per_block - 1) / vecs_per_block;  // 16384
    nora_kernel<<<blocks, threads>>>((const float4*)x, (float4*)d_out, nvec);
}

// round 5
// speedup vs baseline: 1.0788x; 1.0262x over previous
#include <cuda_runtime.h>
#include <cuda_bf16.h>
#include <cstdint>

#define G 8
#define R 3
#define SCALING 2.0f
#define EPS 1e-6f
#define ILP 4

__device__ __forceinline__ float rational_one(float x, const float* __restrict__ c) {
    // P(x) = a0 + a1 x + ... + a5 x^5 (Horner)
    float p = c[5];
    p = fmaf(p, x, c[4]);
    p = fmaf(p, x, c[3]);
    p = fmaf(p, x, c[2]);
    p = fmaf(p, x, c[1]);
    p = fmaf(p, x, c[0]);
    // Z(x) = b0 + b1 x + b2 x^2 + b3 x^3 (Horner), Q = 1 + |Z*x|
    float z = c[9];
    z = fmaf(z, x, c[8]);
    z = fmaf(z, x, c[7]);
    z = fmaf(z, x, c[6]);
    float q = 1.0f + fabsf(z * x);
    return __fdividef(p, q);
}

// x is [B, L, D], D = 4096, G = 8 -> Dg = 512 channels/group = 128 float4s.
// Group of float4 index v: (v >> 7) & 7.
// Coefficient merge (base + SCALING * B@A, EPS folded into denominator) is
// recomputed redundantly per block in the prologue — tiny inputs, L2-resident
// after the first wave — which removes the separate merge launch entirely.
__global__ void __launch_bounds__(256) nora_kernel(const float4* __restrict__ x,
                                                   float4* __restrict__ out,
                                                   const float* __restrict__ base_num,
                                                   const float* __restrict__ base_den,
                                                   const float* __restrict__ lA_num,
                                                   const float* __restrict__ lB_num,
                                                   const float* __restrict__ lA_den,
                                                   const float* __restrict__ lB_den,
                                                   int nvec) {
    __shared__ float sc[80];

    int t = threadIdx.x;
    if (t < G * 10) {
        int g = t / 10;
        int k = t % 10;
        float s;
        if (k < 6) {
            s = base_num[g * 6 + k];
            #pragma unroll
            for (int r = 0; r < R; r++)
                s += SCALING * lB_num[g * R + r] * lA_num[r * 6 + k];
        } else {
            int kk = k - 6;
            s = base_den[g * 4 + kk];
            #pragma unroll
            for (int r = 0; r < R; r++)
                s += SCALING * lB_den[g * R + r] * lA_den[r * 4 + kk];
            s += EPS;
        }
        sc[t] = s;
    }

    // Issue the big streaming loads BEFORE the barrier so the memory pipe is
    // already full while the coefficient threads finish.
    int base = blockIdx.x * (blockDim.x * ILP) + threadIdx.x;

    float4 xi[ILP];
    int    v[ILP];
    #pragma unroll
    for (int k = 0; k < ILP; k++) {
        v[k] = base + k * 256;
        if (v[k] < nvec) xi[k] = __ldcs(&x[v[k]]);
    }

    __syncthreads();

    #pragma unroll
    for (int k = 0; k < ILP; k++) {
        if (v[k] >= nvec) break;
        const float* c = sc + ((v[k] >> 7) & 7) * 10;
        float4 r;
        r.x = rational_one(xi[k].x, c);
        r.y = rational_one(xi[k].y, c);
        r.z = rational_one(xi[k].z, c);
        r.w = rational_one(xi[k].w, c);
        __stcs(&out[v[k]], r);
    }
}

extern "C" void kernel_launch(void* const* d_in, const int* in_sizes, int n_in,
                              void* d_out, int out_size) {
    const float* x        = (const float*)d_in[0];
    const float* base_num = (const float*)d_in[1];
    const float* base_den = (const float*)d_in[2];
    const float* lA_num   = (const float*)d_in[3];
    const float* lB_num   = (const float*)d_in[4];
    const float* lA_den   = (const float*)d_in[5];
    const float* lB_den   = (const float*)d_in[6];

    int n = in_sizes[0];          // 67108864
    int nvec = n >> 2;            // 16777216 float4s
    int threads = 256;
    int vecs_per_block = threads * ILP;
    int blocks = (nvec + vecs_per_block - 1) / vecs_per_block;  // 16384
    nora_kernel<<<blocks, threads>>>((const float4*)x, (float4*)d_out,
                                     base_num, base_den, lA_num, lB_num,
                                     lA_den, lB_den, nvec);
}